// round 3
// baseline (speedup 1.0000x reference)
#include <cuda_runtime.h>

#define N_NODES 50000
#define N_EDGES 800000
#define F 128

// ---- scratch (static device arrays; no allocation allowed) ----
__device__ int   g_counts[N_NODES];
__device__ int   g_offsets[N_NODES + 1];
__device__ int   g_cursor[N_NODES];
__device__ int   g_csr_src[N_EDGES];
__device__ float g_agg[N_NODES * F];
__device__ float g_h[N_NODES * F];

// ---------------- CSR build ----------------
__global__ void zero_counts_kernel() {
    int i = blockIdx.x * blockDim.x + threadIdx.x;
    if (i < N_NODES) g_counts[i] = 0;
}

__global__ void hist_kernel(const int* __restrict__ dst) {
    int i = blockIdx.x * blockDim.x + threadIdx.x;
    if (i < N_EDGES) atomicAdd(&g_counts[dst[i]], 1);
}

// single-block exclusive scan of counts -> offsets (and cursor copy)
__global__ void scan_kernel() {
    __shared__ int part[1024];
    const int CHUNK = (N_NODES + 1023) / 1024;  // 49
    int t = threadIdx.x;
    int lo = t * CHUNK;
    int hi = min(lo + CHUNK, N_NODES);
    int s = 0;
    for (int i = lo; i < hi; i++) s += g_counts[i];
    part[t] = s;
    __syncthreads();
    // Hillis-Steele inclusive scan
    for (int d = 1; d < 1024; d <<= 1) {
        int add = (t >= d) ? part[t - d] : 0;
        __syncthreads();
        part[t] += add;
        __syncthreads();
    }
    int run = (t == 0) ? 0 : part[t - 1];
    for (int i = lo; i < hi; i++) {
        g_offsets[i] = run;
        g_cursor[i]  = run;
        run += g_counts[i];
    }
    if (t == 1023) g_offsets[N_NODES] = run;
}

__global__ void scatter_kernel(const int* __restrict__ src, const int* __restrict__ dst) {
    int i = blockIdx.x * blockDim.x + threadIdx.x;
    if (i < N_EDGES) {
        int p = atomicAdd(&g_cursor[dst[i]], 1);
        g_csr_src[p] = src[i];
    }
}

// ---------------- segment mean (one warp per node) ----------------
__global__ void aggregate_kernel(const float* __restrict__ feat) {
    int warp = (blockIdx.x * blockDim.x + threadIdx.x) >> 5;
    int lane = threadIdx.x & 31;
    if (warp >= N_NODES) return;
    int start = g_offsets[warp];
    int end   = g_offsets[warp + 1];
    const float4* f4 = (const float4*)feat;
    float4 acc = make_float4(0.f, 0.f, 0.f, 0.f);
    int j = start;
    // unroll by 2 for MLP
    for (; j + 1 < end; j += 2) {
        int s0 = g_csr_src[j];
        int s1 = g_csr_src[j + 1];
        float4 v0 = f4[s0 * 32 + lane];
        float4 v1 = f4[s1 * 32 + lane];
        acc.x += v0.x + v1.x; acc.y += v0.y + v1.y;
        acc.z += v0.z + v1.z; acc.w += v0.w + v1.w;
    }
    if (j < end) {
        int s0 = g_csr_src[j];
        float4 v0 = f4[s0 * 32 + lane];
        acc.x += v0.x; acc.y += v0.y; acc.z += v0.z; acc.w += v0.w;
    }
    float inv = 1.0f / (float)max(end - start, 1);
    acc.x *= inv; acc.y *= inv; acc.z *= inv; acc.w *= inv;
    ((float4*)g_agg)[warp * 32 + lane] = acc;
}

// ---------------- fused SAGE layer GEMM ----------------
// out[r][c] = relu( sum_k A0[r][k]*W0[c][k] + sum_k A1[r][k]*W1[c][k] + bias[c] )
// Treated as one M x 128 x 256 GEMM. Tile: 64 rows x 128 cols, 256 threads,
// each thread computes 4x8 outputs. K staged in 32-chunks through smem.
#define MT 64
#define NT 128
#define KT 32

__global__ void __launch_bounds__(256) sage_gemm_kernel(
    const float* __restrict__ A0, const float* __restrict__ A1,
    const float* __restrict__ W0, const float* __restrict__ W1,
    const float* __restrict__ bias, float* __restrict__ out)
{
    __shared__ float As[KT][MT + 4];   // transposed A tile  [k][row]
    __shared__ float Bs[KT][NT + 4];   // transposed W tile  [k][col]

    int tid = threadIdx.x;
    int m0  = blockIdx.x * MT;
    int r0  = (tid >> 4) * 4;        // 0..60 step 4
    int c0  = (tid & 15) * 8;        // 0..120 step 8

    float acc[4][8];
#pragma unroll
    for (int m = 0; m < 4; m++)
#pragma unroll
        for (int n = 0; n < 8; n++) acc[m][n] = 0.f;

#pragma unroll 1
    for (int kt = 0; kt < 8; kt++) {
        const float* A = (kt < 4) ? A0 : A1;
        const float* W = (kt < 4) ? W0 : W1;
        int kb4 = (kt & 3) * 8;      // float4 offset within 128-float row

        // A tile: 64 rows x 32 k = 512 float4, 2 per thread
#pragma unroll
        for (int i = 0; i < 2; i++) {
            int v   = tid + 256 * i;
            int row = v >> 3;
            int kq  = v & 7;
            float4 a = make_float4(0.f, 0.f, 0.f, 0.f);
            int gr = m0 + row;
            if (gr < N_NODES) a = ((const float4*)A)[gr * 32 + kb4 + kq];
            As[kq * 4 + 0][row] = a.x;
            As[kq * 4 + 1][row] = a.y;
            As[kq * 4 + 2][row] = a.z;
            As[kq * 4 + 3][row] = a.w;
        }
        // W tile: 128 cols x 32 k = 1024 float4, 4 per thread
#pragma unroll
        for (int i = 0; i < 4; i++) {
            int v  = tid + 256 * i;
            int c  = v >> 3;
            int kq = v & 7;
            float4 w = ((const float4*)W)[c * 32 + kb4 + kq];
            Bs[kq * 4 + 0][c] = w.x;
            Bs[kq * 4 + 1][c] = w.y;
            Bs[kq * 4 + 2][c] = w.z;
            Bs[kq * 4 + 3][c] = w.w;
        }
        __syncthreads();

#pragma unroll
        for (int k = 0; k < KT; k++) {
            float4 a4 = *(const float4*)&As[k][r0];
            float4 b0 = *(const float4*)&Bs[k][c0];
            float4 b1 = *(const float4*)&Bs[k][c0 + 4];
            float am[4] = {a4.x, a4.y, a4.z, a4.w};
            float bn[8] = {b0.x, b0.y, b0.z, b0.w, b1.x, b1.y, b1.z, b1.w};
#pragma unroll
            for (int m = 0; m < 4; m++)
#pragma unroll
                for (int n = 0; n < 8; n++)
                    acc[m][n] += am[m] * bn[n];
        }
        __syncthreads();
    }

    float bv[8];
#pragma unroll
    for (int n = 0; n < 8; n++) bv[n] = bias[c0 + n];

#pragma unroll
    for (int m = 0; m < 4; m++) {
        int gr = m0 + r0 + m;
        if (gr < N_NODES) {
            float4 o0, o1;
            o0.x = fmaxf(acc[m][0] + bv[0], 0.f);
            o0.y = fmaxf(acc[m][1] + bv[1], 0.f);
            o0.z = fmaxf(acc[m][2] + bv[2], 0.f);
            o0.w = fmaxf(acc[m][3] + bv[3], 0.f);
            o1.x = fmaxf(acc[m][4] + bv[4], 0.f);
            o1.y = fmaxf(acc[m][5] + bv[5], 0.f);
            o1.z = fmaxf(acc[m][6] + bv[6], 0.f);
            o1.w = fmaxf(acc[m][7] + bv[7], 0.f);
            ((float4*)out)[gr * 32 + (c0 >> 2)]     = o0;
            ((float4*)out)[gr * 32 + (c0 >> 2) + 1] = o1;
        }
    }
}

// ---------------- readout ----------------
__global__ void final_kernel(const int* __restrict__ states, int n_states,
                             const int* __restrict__ actions,
                             const float* __restrict__ Wfc,
                             const float* __restrict__ bfc,
                             float* __restrict__ out)
{
    int f = threadIdx.x;  // 128 threads
    float m = -1e30f;
    for (int s = 0; s < n_states; s++)
        m = fmaxf(m, g_h[states[s] * F + f]);
    float av = g_h[actions[0] * F + f];
    float p = m * Wfc[f] + av * Wfc[F + f];
    __shared__ float red[128];
    red[f] = p;
    __syncthreads();
    for (int d = 64; d > 0; d >>= 1) {
        if (f < d) red[f] += red[f + d];
        __syncthreads();
    }
    if (f == 0) out[0] = red[0] + bfc[0];
}

// ---------------- launch ----------------
extern "C" void kernel_launch(void* const* d_in, const int* in_sizes, int n_in,
                              void* d_out, int out_size) {
    const float* x      = (const float*)d_in[0];
    const int*   esrc   = (const int*)d_in[1];
    const int*   edst   = (const int*)d_in[2];
    const int*   states = (const int*)d_in[3];
    const int*   actions= (const int*)d_in[4];
    const float* W1s    = (const float*)d_in[5];
    const float* W1n    = (const float*)d_in[6];
    const float* b1     = (const float*)d_in[7];
    const float* W2s    = (const float*)d_in[8];
    const float* W2n    = (const float*)d_in[9];
    const float* b2     = (const float*)d_in[10];
    const float* Wfc    = (const float*)d_in[11];
    const float* bfc    = (const float*)d_in[12];
    float* out = (float*)d_out;
    int n_states = in_sizes[3];

    float* g_agg_p; cudaGetSymbolAddress((void**)&g_agg_p, g_agg);
    float* g_h_p;   cudaGetSymbolAddress((void**)&g_h_p,   g_h);

    // CSR build (same every call -> deterministic)
    zero_counts_kernel<<<(N_NODES + 255) / 256, 256>>>();
    hist_kernel<<<(N_EDGES + 255) / 256, 256>>>(edst);
    scan_kernel<<<1, 1024>>>();
    scatter_kernel<<<(N_EDGES + 255) / 256, 256>>>(esrc, edst);

    int agg_blocks  = (N_NODES * 32 + 255) / 256;      // one warp per node
    int gemm_blocks = (N_NODES + MT - 1) / MT;

    // layer 1
    aggregate_kernel<<<agg_blocks, 256>>>(x);
    sage_gemm_kernel<<<gemm_blocks, 256>>>(x, g_agg_p, W1s, W1n, b1, g_h_p);
    // layer 2 (in-place over g_h: each block only reads its own row tile)
    aggregate_kernel<<<agg_blocks, 256>>>(g_h_p);
    sage_gemm_kernel<<<gemm_blocks, 256>>>(g_h_p, g_agg_p, W2s, W2n, b2, g_h_p);
    // readout
    final_kernel<<<1, 128>>>(states, n_states, actions, Wfc, bfc, out);
}

// round 4
// speedup vs baseline: 3.7049x; 3.7049x over previous
#include <cuda_runtime.h>

#define N_NODES 50000
#define N_EDGES 800000
#define F 128

// ---- scratch (static device arrays; no allocation allowed) ----
__device__ int   g_flag1[N_NODES];
__device__ int   g_flag2[N_NODES];
__device__ int   g_list1[N_NODES];
__device__ int   g_list2[512];
__device__ int   g_deg[N_NODES];
__device__ int2  g_elist1[N_EDGES];
__device__ int2  g_elist2[N_EDGES];
__device__ int   g_n1, g_n2, g_ne1, g_ne2;
__device__ float g_agg[N_NODES * F];
__device__ float g_h1[N_NODES * F];
__device__ float g_h2[N_NODES * F];

// ---------------- reset flags + counters ----------------
__global__ void reset_kernel() {
    int i = blockIdx.x * blockDim.x + threadIdx.x;
    if (i < N_NODES) { g_flag1[i] = 0; g_flag2[i] = 0; }
    if (i == 0) { g_n1 = 0; g_n2 = 0; g_ne1 = 0; g_ne2 = 0; }
}

// ---------------- build S2 (targets) and seed S1 ----------------
__global__ void build_s2_kernel(const int* __restrict__ states, int n_states,
                                const int* __restrict__ actions) {
    int t = threadIdx.x + blockIdx.x * blockDim.x;
    int node = -1;
    if (t < n_states) node = states[t];
    else if (t == n_states) node = actions[0];
    if (node < 0) return;
    if (atomicExch(&g_flag2[node], 1) == 0) {
        int p = atomicAdd(&g_n2, 1);
        g_list2[p] = node;
    }
    if (atomicExch(&g_flag1[node], 1) == 0) {
        int p = atomicAdd(&g_n1, 1);
        g_list1[p] = node;
    }
}

// ---------------- pass A: edges into S2 -> elist2, sources -> S1 ----------------
__global__ void passA_kernel(const int* __restrict__ src, const int* __restrict__ dst) {
    int i = blockIdx.x * blockDim.x + threadIdx.x;
    if (i >= N_EDGES) return;
    int d = dst[i];
    if (g_flag2[d]) {
        int s = src[i];
        int p = atomicAdd(&g_ne2, 1);
        g_elist2[p] = make_int2(s, d);
        if (atomicExch(&g_flag1[s], 1) == 0) {
            int q = atomicAdd(&g_n1, 1);
            g_list1[q] = s;
        }
    }
}

// ---------------- pass B: edges into S1 -> elist1 ----------------
__global__ void passB_kernel(const int* __restrict__ src, const int* __restrict__ dst) {
    int i = blockIdx.x * blockDim.x + threadIdx.x;
    if (i >= N_EDGES) return;
    int d = dst[i];
    if (g_flag1[d]) {
        int p = atomicAdd(&g_ne1, 1);
        g_elist1[p] = make_int2(src[i], d);
    }
}

// ---------------- zero agg + deg at listed nodes (warp per node) ----------------
__global__ void zero_nodes_kernel(const int* __restrict__ list, const int* __restrict__ count_p) {
    int count = *count_p;
    int nwarps = (gridDim.x * blockDim.x) >> 5;
    int warp = (blockIdx.x * blockDim.x + threadIdx.x) >> 5;
    int lane = threadIdx.x & 31;
    for (int w = warp; w < count; w += nwarps) {
        int node = list[w];
        ((float4*)g_agg)[node * 32 + lane] = make_float4(0.f, 0.f, 0.f, 0.f);
        if (lane == 0) g_deg[node] = 0;
    }
}

// ---------------- edge aggregation: warp per edge, atomic accumulate ----------------
__global__ void edge_agg_kernel(const int2* __restrict__ elist, const int* __restrict__ ne_p,
                                const float* __restrict__ feat) {
    int ne = *ne_p;
    int nwarps = (gridDim.x * blockDim.x) >> 5;
    int warp = (blockIdx.x * blockDim.x + threadIdx.x) >> 5;
    int lane = threadIdx.x & 31;
    for (int j = warp; j < ne; j += nwarps) {
        int2 e = elist[j];
        float4 v = ((const float4*)feat)[e.x * 32 + lane];
        float* a = &g_agg[e.y * F + lane * 4];
        atomicAdd(a + 0, v.x);
        atomicAdd(a + 1, v.y);
        atomicAdd(a + 2, v.z);
        atomicAdd(a + 3, v.w);
        if (lane == 0) atomicAdd(&g_deg[e.y], 1);
    }
}

// ---------------- scale agg by 1/max(deg,1) (warp per node) ----------------
__global__ void scale_kernel(const int* __restrict__ list, const int* __restrict__ count_p) {
    int count = *count_p;
    int nwarps = (gridDim.x * blockDim.x) >> 5;
    int warp = (blockIdx.x * blockDim.x + threadIdx.x) >> 5;
    int lane = threadIdx.x & 31;
    for (int w = warp; w < count; w += nwarps) {
        int node = list[w];
        float inv = 1.0f / (float)max(g_deg[node], 1);
        float4 v = ((float4*)g_agg)[node * 32 + lane];
        v.x *= inv; v.y *= inv; v.z *= inv; v.w *= inv;
        ((float4*)g_agg)[node * 32 + lane] = v;
    }
}

// ---------------- gathered fused SAGE GEMM ----------------
// For each node in list: out[node] = relu(feat[node]@Ws^T + agg[node]@Wn^T + b)
// Tile: 32 gathered rows x 128 cols, 128 threads, 4x8 outputs/thread, K=256.
#define MT 32
#define KT 32

__global__ void __launch_bounds__(128) gemm_list_kernel(
    const int* __restrict__ list, const int* __restrict__ count_p,
    const float* __restrict__ feat,
    const float* __restrict__ Ws, const float* __restrict__ Wn,
    const float* __restrict__ bias, float* __restrict__ out)
{
    int count = *count_p;
    int ntiles = (count + MT - 1) / MT;
    if (blockIdx.x >= ntiles) return;

    __shared__ int   rows[MT];
    __shared__ float As[KT][MT + 4];
    __shared__ float Bs[KT][128 + 4];

    int tid = threadIdx.x;
    int m0  = blockIdx.x * MT;
    int r0  = (tid >> 4) * 4;     // 0..28 step 4
    int c0  = (tid & 15) * 8;     // 0..120 step 8

    if (tid < MT) rows[tid] = (m0 + tid < count) ? list[m0 + tid] : -1;
    __syncthreads();

    float acc[4][8];
#pragma unroll
    for (int m = 0; m < 4; m++)
#pragma unroll
        for (int n = 0; n < 8; n++) acc[m][n] = 0.f;

#pragma unroll 1
    for (int kt = 0; kt < 8; kt++) {
        const float* A = (kt < 4) ? feat : g_agg;
        const float* W = (kt < 4) ? Ws : Wn;
        int kb4 = (kt & 3) * 8;

        // A tile: 32 rows x 32 k = 256 float4, 2 per thread
#pragma unroll
        for (int i = 0; i < 2; i++) {
            int v   = tid + 128 * i;
            int row = v >> 3;
            int kq  = v & 7;
            int nd  = rows[row];
            float4 a = make_float4(0.f, 0.f, 0.f, 0.f);
            if (nd >= 0) a = ((const float4*)A)[nd * 32 + kb4 + kq];
            As[kq * 4 + 0][row] = a.x;
            As[kq * 4 + 1][row] = a.y;
            As[kq * 4 + 2][row] = a.z;
            As[kq * 4 + 3][row] = a.w;
        }
        // W tile: 128 cols x 32 k = 1024 float4, 8 per thread
#pragma unroll
        for (int i = 0; i < 8; i++) {
            int v  = tid + 128 * i;
            int c  = v >> 3;
            int kq = v & 7;
            float4 w = ((const float4*)W)[c * 32 + kb4 + kq];
            Bs[kq * 4 + 0][c] = w.x;
            Bs[kq * 4 + 1][c] = w.y;
            Bs[kq * 4 + 2][c] = w.z;
            Bs[kq * 4 + 3][c] = w.w;
        }
        __syncthreads();

#pragma unroll
        for (int k = 0; k < KT; k++) {
            float4 a4 = *(const float4*)&As[k][r0];
            float4 b0 = *(const float4*)&Bs[k][c0];
            float4 b1 = *(const float4*)&Bs[k][c0 + 4];
            float am[4] = {a4.x, a4.y, a4.z, a4.w};
            float bn[8] = {b0.x, b0.y, b0.z, b0.w, b1.x, b1.y, b1.z, b1.w};
#pragma unroll
            for (int m = 0; m < 4; m++)
#pragma unroll
                for (int n = 0; n < 8; n++)
                    acc[m][n] += am[m] * bn[n];
        }
        __syncthreads();
    }

    float bv[8];
#pragma unroll
    for (int n = 0; n < 8; n++) bv[n] = bias[c0 + n];

#pragma unroll
    for (int m = 0; m < 4; m++) {
        int nd = rows[r0 + m];
        if (nd >= 0) {
            float4 o0, o1;
            o0.x = fmaxf(acc[m][0] + bv[0], 0.f);
            o0.y = fmaxf(acc[m][1] + bv[1], 0.f);
            o0.z = fmaxf(acc[m][2] + bv[2], 0.f);
            o0.w = fmaxf(acc[m][3] + bv[3], 0.f);
            o1.x = fmaxf(acc[m][4] + bv[4], 0.f);
            o1.y = fmaxf(acc[m][5] + bv[5], 0.f);
            o1.z = fmaxf(acc[m][6] + bv[6], 0.f);
            o1.w = fmaxf(acc[m][7] + bv[7], 0.f);
            ((float4*)out)[nd * 32 + (c0 >> 2)]     = o0;
            ((float4*)out)[nd * 32 + (c0 >> 2) + 1] = o1;
        }
    }
}

// ---------------- readout ----------------
__global__ void final_kernel(const int* __restrict__ states, int n_states,
                             const int* __restrict__ actions,
                             const float* __restrict__ Wfc,
                             const float* __restrict__ bfc,
                             float* __restrict__ out)
{
    int f = threadIdx.x;  // 128 threads
    float m = -1e30f;
    for (int s = 0; s < n_states; s++)
        m = fmaxf(m, g_h2[states[s] * F + f]);
    float av = g_h2[actions[0] * F + f];
    float p = m * Wfc[f] + av * Wfc[F + f];
    __shared__ float red[128];
    red[f] = p;
    __syncthreads();
    for (int d = 64; d > 0; d >>= 1) {
        if (f < d) red[f] += red[f + d];
        __syncthreads();
    }
    if (f == 0) out[0] = red[0] + bfc[0];
}

// ---------------- launch ----------------
extern "C" void kernel_launch(void* const* d_in, const int* in_sizes, int n_in,
                              void* d_out, int out_size) {
    const float* x      = (const float*)d_in[0];
    const int*   esrc   = (const int*)d_in[1];
    const int*   edst   = (const int*)d_in[2];
    const int*   states = (const int*)d_in[3];
    const int*   actions= (const int*)d_in[4];
    const float* W1s    = (const float*)d_in[5];
    const float* W1n    = (const float*)d_in[6];
    const float* b1     = (const float*)d_in[7];
    const float* W2s    = (const float*)d_in[8];
    const float* W2n    = (const float*)d_in[9];
    const float* b2     = (const float*)d_in[10];
    const float* Wfc    = (const float*)d_in[11];
    const float* bfc    = (const float*)d_in[12];
    float* out = (float*)d_out;
    int n_states = in_sizes[3];

    int *list1_p, *list2_p, *n1_p, *n2_p, *ne1_p, *ne2_p;
    int2 *elist1_p, *elist2_p;
    float *h1_p, *h2_p;
    cudaGetSymbolAddress((void**)&list1_p,  g_list1);
    cudaGetSymbolAddress((void**)&list2_p,  g_list2);
    cudaGetSymbolAddress((void**)&n1_p,     g_n1);
    cudaGetSymbolAddress((void**)&n2_p,     g_n2);
    cudaGetSymbolAddress((void**)&ne1_p,    g_ne1);
    cudaGetSymbolAddress((void**)&ne2_p,    g_ne2);
    cudaGetSymbolAddress((void**)&elist1_p, g_elist1);
    cudaGetSymbolAddress((void**)&elist2_p, g_elist2);
    cudaGetSymbolAddress((void**)&h1_p,     g_h1);
    cudaGetSymbolAddress((void**)&h2_p,     g_h2);

    // frontier construction
    reset_kernel<<<(N_NODES + 255) / 256, 256>>>();
    build_s2_kernel<<<2, 256>>>(states, n_states, actions);
    passA_kernel<<<(N_EDGES + 255) / 256, 256>>>(esrc, edst);
    passB_kernel<<<(N_EDGES + 255) / 256, 256>>>(esrc, edst);

    // layer 1 (nodes in S1)
    zero_nodes_kernel<<<1024, 256>>>(list1_p, n1_p);
    edge_agg_kernel<<<2048, 256>>>(elist1_p, ne1_p, x);
    scale_kernel<<<512, 256>>>(list1_p, n1_p);
    gemm_list_kernel<<<(N_NODES + MT - 1) / MT, 128>>>(list1_p, n1_p, x, W1s, W1n, b1, h1_p);

    // layer 2 (nodes in S2)
    zero_nodes_kernel<<<33, 256>>>(list2_p, n2_p);
    edge_agg_kernel<<<2048, 256>>>(elist2_p, ne2_p, h1_p);
    scale_kernel<<<33, 256>>>(list2_p, n2_p);
    gemm_list_kernel<<<9, 128>>>(list2_p, n2_p, h1_p, W2s, W2n, b2, h2_p);

    // readout
    final_kernel<<<1, 128>>>(states, n_states, actions, Wfc, bfc, out);
}

// round 6
// speedup vs baseline: 3.9462x; 1.0651x over previous
#include <cuda_runtime.h>

#define N_NODES 50000
#define N_EDGES 800000
#define F 128

// ---- scratch (static device arrays; no allocation allowed) ----
__device__ int   g_flag1[N_NODES];
__device__ int   g_flag2[N_NODES];
__device__ int   g_list1[N_NODES];
__device__ int   g_list2[512];
__device__ int   g_deg1[N_NODES];
__device__ int   g_deg2[N_NODES];
__device__ int2  g_elist1[N_EDGES];
__device__ int2  g_elist2[N_EDGES];
__device__ int   g_n1, g_n2, g_ne1, g_ne2;
__device__ float g_agg[N_NODES * F];
__device__ float g_h1[N_NODES * F];
__device__ float g_h2[N_NODES * F];

// ---------------- reset flags + degs + counters ----------------
__global__ void reset_kernel() {
    int i = blockIdx.x * blockDim.x + threadIdx.x;
    if (i < N_NODES) {
        g_flag1[i] = 0; g_flag2[i] = 0;
        g_deg1[i] = 0;  g_deg2[i] = 0;
    }
    if (i == 0) { g_n1 = 0; g_n2 = 0; g_ne1 = 0; g_ne2 = 0; }
}

// ---------------- build S2 (targets) and seed S1 ----------------
__global__ void build_s2_kernel(const int* __restrict__ states, int n_states,
                                const int* __restrict__ actions) {
    int t = threadIdx.x + blockIdx.x * blockDim.x;
    int node = -1;
    if (t < n_states) node = states[t];
    else if (t == n_states) node = actions[0];
    if (node < 0) return;
    if (atomicExch(&g_flag2[node], 1) == 0) {
        int p = atomicAdd(&g_n2, 1);
        g_list2[p] = node;
    }
    if (atomicExch(&g_flag1[node], 1) == 0) {
        int p = atomicAdd(&g_n1, 1);
        g_list1[p] = node;
    }
}

// ---------------- pass A: edges into S2 -> elist2 (+deg2), sources -> S1 ----------------
// 4 edges per thread; hierarchical counter aggregation (warp scan -> shared -> 1 global)
__global__ void __launch_bounds__(256) passA_kernel(const int* __restrict__ src,
                                                    const int* __restrict__ dst) {
    __shared__ int s_cnt, s_base;
    if (threadIdx.x == 0) s_cnt = 0;
    __syncthreads();

    int i4 = blockIdx.x * blockDim.x + threadIdx.x;     // quad index
    int lane = threadIdx.x & 31;
    bool valid = (i4 * 4 < N_EDGES);
    int4 d4 = valid ? ((const int4*)dst)[i4] : make_int4(0,0,0,0);
    int4 s4 = valid ? ((const int4*)src)[i4] : make_int4(0,0,0,0);
    int dv[4] = {d4.x, d4.y, d4.z, d4.w};
    int sv[4] = {s4.x, s4.y, s4.z, s4.w};
    bool pass[4];
    int my = 0;
#pragma unroll
    for (int j = 0; j < 4; j++) {
        pass[j] = valid && g_flag2[dv[j]];
        my += pass[j] ? 1 : 0;
    }
    // warp inclusive scan of per-thread counts
    int scan = my;
#pragma unroll
    for (int d = 1; d < 32; d <<= 1) {
        int t = __shfl_up_sync(0xffffffff, scan, d);
        if (lane >= d) scan += t;
    }
    int wtotal = __shfl_sync(0xffffffff, scan, 31);
    int wbase = 0;
    if (lane == 31 && wtotal > 0) wbase = atomicAdd(&s_cnt, wtotal);
    wbase = __shfl_sync(0xffffffff, wbase, 31);
    int my_off = wbase + scan - my;
    __syncthreads();
    if (threadIdx.x == 0) s_base = (s_cnt > 0) ? atomicAdd(&g_ne2, s_cnt) : 0;
    __syncthreads();
    int p = s_base + my_off;
#pragma unroll
    for (int j = 0; j < 4; j++) {
        if (pass[j]) {
            g_elist2[p++] = make_int2(sv[j], dv[j]);
            atomicAdd(&g_deg2[dv[j]], 1);
            if (atomicExch(&g_flag1[sv[j]], 1) == 0) {
                int q = atomicAdd(&g_n1, 1);
                g_list1[q] = sv[j];
            }
        }
    }
}

// ---------------- pass B: edges into S1 -> elist1 (+deg1) ----------------
__global__ void __launch_bounds__(256) passB_kernel(const int* __restrict__ src,
                                                    const int* __restrict__ dst) {
    __shared__ int s_cnt, s_base;
    if (threadIdx.x == 0) s_cnt = 0;
    __syncthreads();

    int i4 = blockIdx.x * blockDim.x + threadIdx.x;
    int lane = threadIdx.x & 31;
    bool valid = (i4 * 4 < N_EDGES);
    int4 d4 = valid ? ((const int4*)dst)[i4] : make_int4(0,0,0,0);
    int4 s4 = valid ? ((const int4*)src)[i4] : make_int4(0,0,0,0);
    int dv[4] = {d4.x, d4.y, d4.z, d4.w};
    int sv[4] = {s4.x, s4.y, s4.z, s4.w};
    bool pass[4];
    int my = 0;
#pragma unroll
    for (int j = 0; j < 4; j++) {
        pass[j] = valid && g_flag1[dv[j]];
        my += pass[j] ? 1 : 0;
    }
    int scan = my;
#pragma unroll
    for (int d = 1; d < 32; d <<= 1) {
        int t = __shfl_up_sync(0xffffffff, scan, d);
        if (lane >= d) scan += t;
    }
    int wtotal = __shfl_sync(0xffffffff, scan, 31);
    int wbase = 0;
    if (lane == 31 && wtotal > 0) wbase = atomicAdd(&s_cnt, wtotal);
    wbase = __shfl_sync(0xffffffff, wbase, 31);
    int my_off = wbase + scan - my;
    __syncthreads();
    if (threadIdx.x == 0) s_base = (s_cnt > 0) ? atomicAdd(&g_ne1, s_cnt) : 0;
    __syncthreads();
    int p = s_base + my_off;
#pragma unroll
    for (int j = 0; j < 4; j++) {
        if (pass[j]) {
            g_elist1[p++] = make_int2(sv[j], dv[j]);
            atomicAdd(&g_deg1[dv[j]], 1);
        }
    }
}

// ---------------- zero agg at listed nodes (warp per node) ----------------
__global__ void zero_agg_kernel(const int* __restrict__ list, const int* __restrict__ count_p) {
    int count = *count_p;
    int nwarps = (gridDim.x * blockDim.x) >> 5;
    int warp = (blockIdx.x * blockDim.x + threadIdx.x) >> 5;
    int lane = threadIdx.x & 31;
    for (int w = warp; w < count; w += nwarps) {
        int node = list[w];
        ((float4*)g_agg)[node * 32 + lane] = make_float4(0.f, 0.f, 0.f, 0.f);
    }
}

// ---------------- edge aggregation: warp per edge, vector red ----------------
__global__ void edge_agg_kernel(const int2* __restrict__ elist, const int* __restrict__ ne_p,
                                const float* __restrict__ feat) {
    int ne = *ne_p;
    int nwarps = (gridDim.x * blockDim.x) >> 5;
    int warp = (blockIdx.x * blockDim.x + threadIdx.x) >> 5;
    int lane = threadIdx.x & 31;
    for (int j = warp; j < ne; j += nwarps) {
        int2 e = elist[j];
        float4 v = ((const float4*)feat)[e.x * 32 + lane];
        float* a = &g_agg[e.y * F + lane * 4];
#if __CUDA_ARCH__ >= 900
        asm volatile("red.global.add.v4.f32 [%0], {%1, %2, %3, %4};"
                     :: "l"(a), "f"(v.x), "f"(v.y), "f"(v.z), "f"(v.w) : "memory");
#else
        atomicAdd(a + 0, v.x); atomicAdd(a + 1, v.y);
        atomicAdd(a + 2, v.z); atomicAdd(a + 3, v.w);
#endif
    }
}

// ---------------- gathered fused SAGE GEMM (1/deg scaling fused into A load) --
// out[node] = relu(feat[node]@Ws^T + (agg[node]/max(deg,1))@Wn^T + b)
#define MT 32
#define KT 32

__global__ void __launch_bounds__(128) gemm_list_kernel(
    const int* __restrict__ list, const int* __restrict__ count_p,
    const float* __restrict__ feat, const int* __restrict__ deg,
    const float* __restrict__ Ws, const float* __restrict__ Wn,
    const float* __restrict__ bias, float* __restrict__ out)
{
    int count = *count_p;
    int ntiles = (count + MT - 1) / MT;
    if (blockIdx.x >= ntiles) return;

    __shared__ int   rows[MT];
    __shared__ float invs[MT];
    __shared__ float As[KT][MT + 4];
    __shared__ float Bs[KT][128 + 4];

    int tid = threadIdx.x;
    int m0  = blockIdx.x * MT;
    int r0  = (tid >> 4) * 4;     // 0..28 step 4
    int c0  = (tid & 15) * 8;     // 0..120 step 8

    if (tid < MT) {
        int nd = (m0 + tid < count) ? list[m0 + tid] : -1;
        rows[tid] = nd;
        invs[tid] = (nd >= 0) ? 1.0f / (float)max(deg[nd], 1) : 0.f;
    }
    __syncthreads();

    float acc[4][8];
#pragma unroll
    for (int m = 0; m < 4; m++)
#pragma unroll
        for (int n = 0; n < 8; n++) acc[m][n] = 0.f;

#pragma unroll 1
    for (int kt = 0; kt < 8; kt++) {
        const float* A = (kt < 4) ? feat : g_agg;
        const float* W = (kt < 4) ? Ws : Wn;
        int kb4 = (kt & 3) * 8;

        // A tile: 32 rows x 32 k = 256 float4, 2 per thread (scaled if agg half)
#pragma unroll
        for (int i = 0; i < 2; i++) {
            int v   = tid + 128 * i;
            int row = v >> 3;
            int kq  = v & 7;
            int nd  = rows[row];
            float4 a = make_float4(0.f, 0.f, 0.f, 0.f);
            if (nd >= 0) a = ((const float4*)A)[nd * 32 + kb4 + kq];
            float sc = (kt < 4) ? 1.0f : invs[row];
            As[kq * 4 + 0][row] = a.x * sc;
            As[kq * 4 + 1][row] = a.y * sc;
            As[kq * 4 + 2][row] = a.z * sc;
            As[kq * 4 + 3][row] = a.w * sc;
        }
        // W tile: 128 cols x 32 k = 1024 float4, 8 per thread
#pragma unroll
        for (int i = 0; i < 8; i++) {
            int v  = tid + 128 * i;
            int c  = v >> 3;
            int kq = v & 7;
            float4 w = ((const float4*)W)[c * 32 + kb4 + kq];
            Bs[kq * 4 + 0][c] = w.x;
            Bs[kq * 4 + 1][c] = w.y;
            Bs[kq * 4 + 2][c] = w.z;
            Bs[kq * 4 + 3][c] = w.w;
        }
        __syncthreads();

#pragma unroll
        for (int k = 0; k < KT; k++) {
            float4 a4 = *(const float4*)&As[k][r0];
            float4 b0 = *(const float4*)&Bs[k][c0];
            float4 b1 = *(const float4*)&Bs[k][c0 + 4];
            float am[4] = {a4.x, a4.y, a4.z, a4.w};
            float bn[8] = {b0.x, b0.y, b0.z, b0.w, b1.x, b1.y, b1.z, b1.w};
#pragma unroll
            for (int m = 0; m < 4; m++)
#pragma unroll
                for (int n = 0; n < 8; n++)
                    acc[m][n] += am[m] * bn[n];
        }
        __syncthreads();
    }

    float bv[8];
#pragma unroll
    for (int n = 0; n < 8; n++) bv[n] = bias[c0 + n];

#pragma unroll
    for (int m = 0; m < 4; m++) {
        int nd = rows[r0 + m];
        if (nd >= 0) {
            float4 o0, o1;
            o0.x = fmaxf(acc[m][0] + bv[0], 0.f);
            o0.y = fmaxf(acc[m][1] + bv[1], 0.f);
            o0.z = fmaxf(acc[m][2] + bv[2], 0.f);
            o0.w = fmaxf(acc[m][3] + bv[3], 0.f);
            o1.x = fmaxf(acc[m][4] + bv[4], 0.f);
            o1.y = fmaxf(acc[m][5] + bv[5], 0.f);
            o1.z = fmaxf(acc[m][6] + bv[6], 0.f);
            o1.w = fmaxf(acc[m][7] + bv[7], 0.f);
            ((float4*)out)[nd * 32 + (c0 >> 2)]     = o0;
            ((float4*)out)[nd * 32 + (c0 >> 2) + 1] = o1;
        }
    }
}

// ---------------- readout ----------------
__global__ void final_kernel(const int* __restrict__ states, int n_states,
                             const int* __restrict__ actions,
                             const float* __restrict__ Wfc,
                             const float* __restrict__ bfc,
                             float* __restrict__ out)
{
    int f = threadIdx.x;  // 128 threads
    float m = -1e30f;
#pragma unroll 4
    for (int s = 0; s < n_states; s++)
        m = fmaxf(m, g_h2[states[s] * F + f]);
    float av = g_h2[actions[0] * F + f];
    float p = m * Wfc[f] + av * Wfc[F + f];
    __shared__ float red[128];
    red[f] = p;
    __syncthreads();
    for (int d = 64; d > 0; d >>= 1) {
        if (f < d) red[f] += red[f + d];
        __syncthreads();
    }
    if (f == 0) out[0] = red[0] + bfc[0];
}

// ---------------- launch ----------------
extern "C" void kernel_launch(void* const* d_in, const int* in_sizes, int n_in,
                              void* d_out, int out_size) {
    const float* x      = (const float*)d_in[0];
    const int*   esrc   = (const int*)d_in[1];
    const int*   edst   = (const int*)d_in[2];
    const int*   states = (const int*)d_in[3];
    const int*   actions= (const int*)d_in[4];
    const float* W1s    = (const float*)d_in[5];
    const float* W1n    = (const float*)d_in[6];
    const float* b1     = (const float*)d_in[7];
    const float* W2s    = (const float*)d_in[8];
    const float* W2n    = (const float*)d_in[9];
    const float* b2     = (const float*)d_in[10];
    const float* Wfc    = (const float*)d_in[11];
    const float* bfc    = (const float*)d_in[12];
    float* out = (float*)d_out;
    int n_states = in_sizes[3];

    int *list1_p, *list2_p, *n1_p, *n2_p, *ne1_p, *ne2_p, *deg1_p, *deg2_p;
    int2 *elist1_p, *elist2_p;
    float *h1_p, *h2_p;
    cudaGetSymbolAddress((void**)&list1_p,  g_list1);
    cudaGetSymbolAddress((void**)&list2_p,  g_list2);
    cudaGetSymbolAddress((void**)&n1_p,     g_n1);
    cudaGetSymbolAddress((void**)&n2_p,     g_n2);
    cudaGetSymbolAddress((void**)&ne1_p,    g_ne1);
    cudaGetSymbolAddress((void**)&ne2_p,    g_ne2);
    cudaGetSymbolAddress((void**)&deg1_p,   g_deg1);
    cudaGetSymbolAddress((void**)&deg2_p,   g_deg2);
    cudaGetSymbolAddress((void**)&elist1_p, g_elist1);
    cudaGetSymbolAddress((void**)&elist2_p, g_elist2);
    cudaGetSymbolAddress((void**)&h1_p,     g_h1);
    cudaGetSymbolAddress((void**)&h2_p,     g_h2);

    const int QUADS = N_EDGES / 4;                 // 200000
    const int pass_blocks = (QUADS + 255) / 256;   // 782

    // frontier construction
    reset_kernel<<<(N_NODES + 255) / 256, 256>>>();
    build_s2_kernel<<<2, 256>>>(states, n_states, actions);
    passA_kernel<<<pass_blocks, 256>>>(esrc, edst);
    passB_kernel<<<pass_blocks, 256>>>(esrc, edst);

    // layer 1 (nodes in S1)
    zero_agg_kernel<<<256, 256>>>(list1_p, n1_p);
    edge_agg_kernel<<<1024, 256>>>(elist1_p, ne1_p, x);
    gemm_list_kernel<<<(N_NODES + MT - 1) / MT, 128>>>(list1_p, n1_p, x, deg1_p,
                                                       W1s, W1n, b1, h1_p);

    // layer 2 (nodes in S2)
    zero_agg_kernel<<<33, 256>>>(list2_p, n2_p);
    edge_agg_kernel<<<1024, 256>>>(elist2_p, ne2_p, h1_p);
    gemm_list_kernel<<<9, 128>>>(list2_p, n2_p, h1_p, deg2_p, W2s, W2n, b2, h2_p);

    // readout
    final_kernel<<<1, 128>>>(states, n_states, actions, Wfc, bfc, out);
}